// round 12
// baseline (speedup 1.0000x reference)
#include <cuda_runtime.h>
#include <cuda_fp16.h>
#include <cstdint>

#define BATCH 32
#define CH    256
#define HW    3136

// per-(b, f_half) stride in g_W: 144 k16_tiles * 2048 halves
#define WHALF 294912ull

// ---------------- scratch (device globals; no runtime allocation) ----------
__device__ float  g_maxi[BATCH * CH * 25];
__device__ float  g_wgt1[BATCH * CH * 9];
// fp16 weights in m16n8k16 fragment order:
// [b][f_half(2)][k16_tile(144)][f_tile(8)][lane(32)][reg(4)x half(2)]
__device__ __half g_W[(size_t)BATCH * CH * 9 * CH];

__constant__ int c_bin_start[5] = {0, 11, 22, 33, 44};

// ============================================================================
// Kernel 1: adaptive avg+max pool 56x56 -> 5x5, fused depthwise 3x3+relu.
// 512 threads; band reduction split 2-way over rows (6 rows per task),
// 560 tasks covered by a strided loop (fixes R11's missing-guard bug).
// ============================================================================
__global__ __launch_bounds__(512) void pool_kernel(
    const float* __restrict__ x, const float* __restrict__ w1,
    const float* __restrict__ b1)
{
    __shared__ float img[HW];
    __shared__ float rs[5][56][2], rm[5][56][2];
    __shared__ float avgb[25];
    int bc = blockIdx.x, c = bc & 255, t = threadIdx.x;

    const float4* src4 = (const float4*)(x + (size_t)bc * HW);
    float4* img4 = (float4*)img;
    for (int i = t; i < HW / 4; i += 512) img4[i] = src4[i];
    __syncthreads();

    for (int task = t; task < 560; task += 512) {
        int half = task >= 280, t2 = task - half * 280;
        int band = t2 / 56, col = t2 - band * 56;
        int r0 = c_bin_start[band] + half * 6;
        float s = 0.f, m = -3.402823466e38f;
        #pragma unroll
        for (int r = 0; r < 6; r++) {
            float v = img[(r0 + r) * 56 + col];
            s += v; m = fmaxf(m, v);
        }
        rs[band][col][half] = s; rm[band][col][half] = m;
    }
    __syncthreads();

    if (t < 25) {
        int bi = t / 5, bj = t % 5;
        int c0 = c_bin_start[bj];
        float s = 0.f, m = -3.402823466e38f;
        #pragma unroll
        for (int k = 0; k < 12; k++) {
            s += rs[bi][c0 + k][0] + rs[bi][c0 + k][1];
            m = fmaxf(m, fmaxf(rm[bi][c0 + k][0], rm[bi][c0 + k][1]));
        }
        avgb[t] = s * (1.f / 144.f);
        g_maxi[bc * 25 + t] = m;
    }
    __syncthreads();

    if (t < 9) {
        int u = t / 3, v = t % 3;
        float acc = b1[c];
        #pragma unroll
        for (int i = 0; i < 3; i++)
            #pragma unroll
            for (int j = 0; j < 3; j++)
                acc += avgb[(u + i) * 5 + (v + j)] * w1[c * 9 + i * 3 + j];
        g_wgt1[bc * 9 + t] = fmaxf(acc, 0.f);
    }
}

// ============================================================================
// Kernel 2: weight generation, scatter-stored fp16 in m16n8k16 fragment order.
// ============================================================================
__global__ __launch_bounds__(256) void gen_kernel(
    const float* __restrict__ w2, const float* __restrict__ b2,
    const float* __restrict__ w_att, const float* __restrict__ b_att)
{
    int p = blockIdx.x, b = blockIdx.y, q = threadIdx.x;
    int bp = b * CH + p;

    __shared__ float maxi_s[25];
    __shared__ float wgt1_s[9];
    if (q < 25) maxi_s[q] = g_maxi[bp * 25 + q];
    if (q >= 32 && q < 41) wgt1_s[q - 32] = g_wgt1[bp * 9 + (q - 32)];
    __syncthreads();

    int cidx = p * CH + q;
    float wa[9];
    #pragma unroll
    for (int k = 0; k < 9; k++) wa[k] = w_att[cidx * 9 + k];
    float w2c = w2[cidx], b2c = b2[cidx], bac = b_att[cidx];

    int cg = q >> 5, ci = q & 31;
    int fh = p >> 7, fr = p & 127, ft = fr >> 4;
    int kk = ci & 15;
    int lane = ((fr & 7) << 2) | ((kk & 7) >> 1);
    int reg  = ((fr >> 3) & 1) | ((kk >> 3) << 1);
    int h    = kk & 1;
    __half* base = g_W + ((size_t)b * 2 + fh) * WHALF;
    size_t elem = ((size_t)ft * 32 + lane) * 8 + reg * 2 + h;

    #pragma unroll
    for (int u = 0; u < 3; u++)
        #pragma unroll
        for (int v = 0; v < 3; v++) {
            float s = bac;
            #pragma unroll
            for (int i = 0; i < 3; i++)
                #pragma unroll
                for (int j = 0; j < 3; j++)
                    s += maxi_s[(u + i) * 5 + (v + j)] * wa[i * 3 + j];
            float att = 1.f / (1.f + __expf(-s));
            float val = (wgt1_s[u * 3 + v] * w2c + b2c) * att;
            int tap = u * 3 + v;
            int kt = (cg * 9 + tap) * 2 + (ci >> 4);
            base[(size_t)kt * 2048 + elem] = __float2half_rn(val);
        }
}

// ============================================================================
// helpers
// ============================================================================
__device__ __forceinline__ uint32_t smem_u32(const void* p) {
    uint32_t a;
    asm("{ .reg .u64 t; cvta.to.shared.u64 t, %1; cvt.u32.u64 %0, t; }" : "=r"(a) : "l"(p));
    return a;
}
__device__ __forceinline__ uint32_t pkh2(float lo, float hi) {
    __half2 h = __floats2half2_rn(lo, hi);
    return *(uint32_t*)&h;
}
__device__ __forceinline__ void mma16(float* d, const uint4 a,
                                      uint32_t b0, uint32_t b1) {
    asm volatile(
        "mma.sync.aligned.m16n8k16.row.col.f32.f16.f16.f32 "
        "{%0,%1,%2,%3}, {%4,%5,%6,%7}, {%8,%9}, {%0,%1,%2,%3};"
        : "+f"(d[0]), "+f"(d[1]), "+f"(d[2]), "+f"(d[3])
        : "r"(a.x), "r"(a.y), "r"(a.z), "r"(a.w), "r"(b0), "r"(b1));
}
__device__ __forceinline__ void cpasync16(uint32_t dst, const void* src) {
    asm volatile("cp.async.cg.shared.global [%0], [%1], 16;" :: "r"(dst), "l"(src));
}
#define CP_COMMIT() asm volatile("cp.async.commit_group;" ::: "memory")
#define CP_WAIT0()  asm volatile("cp.async.wait_group 0;" ::: "memory")
#define CP_WAIT1()  asm volatile("cp.async.wait_group 1;" ::: "memory")

// ============================================================================
// Kernel 3: fp16 m16n8k16 mma.sync implicit GEMM, fragment-order A.
// CTA = (b, f_half 128 filters, 4 rows x 56 px). Warps 2(M) x 4(N).
// Triple-buffered A stages (3 taps = 24KB linear), prefetch depth 2,
// wait_group 1 consume points. x window packed fp16x2 channel pairs.
// ============================================================================
#define XWS     360                // uint32 stride per cpair
#define OFF_XR  23040              // xw32: 16*360*4 B
#define OFF_A   66048              // xraw: 32*84*16 = 43008 B
#define A_BUF   24576              // 6 kt * 2048 halves * 2 B
#define CONV_SMEM (OFF_A + 3 * A_BUF)   // 139776 B

__global__ void __launch_bounds__(256, 1)
conv_mma(const float* __restrict__ x, float* __restrict__ out)
{
    extern __shared__ char smem[];
    uint32_t* xw32 = (uint32_t*)smem;
    float* xraw = (float*)(smem + OFF_XR);
    const uint32_t sb = smem_u32(smem);
    const int tid = threadIdx.x, lid = tid & 31, wid = tid >> 5;
    const int g = lid >> 2, t4 = lid & 3;
    const int warpM = wid & 1, warpN = wid >> 1;    // 2 x 4
    const int b = blockIdx.z, fh = blockIdx.y, row0 = blockIdx.x * 4;

    const float* xb = x + (size_t)b * CH * HW;
    const __half* wb = g_W + ((size_t)b * 2 + fh) * WHALF;

    float d[4][7][4];
    #pragma unroll
    for (int i = 0; i < 4; i++)
        #pragma unroll
        for (int j = 0; j < 7; j++)
            #pragma unroll
            for (int k = 0; k < 4; k++) d[i][j][k] = 0.f;

    // ---- A stage: 24KB linear copy (stage = 3 taps = 6 k16-tiles) ----
    auto stageA = [&](int stageIdx, int buf) {
        const __half* src = wb + (size_t)stageIdx * 12288;
        uint32_t dbase = sb + OFF_A + (uint32_t)buf * A_BUF;
        #pragma unroll
        for (int i = 0; i < 6; ++i) {
            int idx = i * 256 + tid;
            cpasync16(dbase + (uint32_t)idx * 16, src + idx * 8);
        }
        CP_COMMIT();
    };
    // ---- X prefetch: raw 32-ch fp32 window -> xraw ----
    auto stageX = [&](int cg) {
        for (int i = tid; i < 32 * 84; i += 256) {
            int c2 = i / 84, rem = i - c2 * 84;
            int rw = rem / 14, gq = rem - rw * 14;
            int grow = row0 - 1 + rw;
            if ((unsigned)grow < 56u)
                cpasync16(sb + OFF_XR + (uint32_t)i * 16,
                          xb + (size_t)(cg * 32 + c2) * HW + grow * 56 + 4 * gq);
        }
        CP_COMMIT();
    };

    // zero packed window once (halo stays zero)
    for (int i = tid; i < (16 * XWS) / 4; i += 256)
        ((uint4*)xw32)[i] = make_uint4(0, 0, 0, 0);
    // prologue: pending queue = { X0, A0, A1 }
    stageX(0);
    stageA(0, 0);
    stageA(1, 1);

    int stage = 0;
    for (int cg = 0; cg < 8; ++cg) {
        // need X(cg) and A(3cg) resident; leave A(3cg+1) pending
        CP_WAIT1();
        __syncthreads();
        // ---- pack raw fp32 -> fp16x2 channel pairs ----
        for (int i = tid; i < 16 * 84; i += 256) {
            int cp = i / 84, rem = i - cp * 84;
            int rw = rem / 14, gq = rem - rw * 14;
            int grow = row0 - 1 + rw;
            if ((unsigned)grow < 56u) {
                float4 va = ((const float4*)xraw)[(2 * cp) * 84 + rem];
                float4 vb = ((const float4*)xraw)[(2 * cp + 1) * 84 + rem];
                uint32_t* dst = xw32 + cp * XWS + rw * 58 + 4 * gq + 1;
                dst[0] = pkh2(va.x, vb.x);
                dst[1] = pkh2(va.y, vb.y);
                dst[2] = pkh2(va.z, vb.z);
                dst[3] = pkh2(va.w, vb.w);
            }
        }
        __syncthreads();

        for (int s = 0; s < 3; ++s, ++stage) {
            if (s > 0) {                        // A(stage) must be resident
                if (stage == 23) CP_WAIT0(); else CP_WAIT1();
                __syncthreads();
            }
            // commits (overlap with compute below); X before next cg's A
            if (s == 2 && cg < 7) stageX(cg + 1);
            if (stage + 2 < 24) stageA(stage + 2, (stage + 2) % 3);

            const uint32_t* as =
                (const uint32_t*)(smem + OFF_A + (stage % 3) * A_BUF);
            #pragma unroll
            for (int tapo = 0; tapo < 3; ++tapo) {
                const int tap = s * 3 + tapo;
                const int ti = tap / 3, tj = tap - ti * 3;
                #pragma unroll
                for (int ksh = 0; ksh < 2; ++ksh) {
                    uint4 A[4];
                    const uint32_t* abase = as
                        + ((tapo * 2 + ksh) * 8 + warpM * 4) * 128 + lid * 4;
                    #pragma unroll
                    for (int mf = 0; mf < 4; ++mf)
                        A[mf] = *(const uint4*)(abase + mf * 128);
                    const uint32_t* bbase = xw32 + (ksh * 8 + t4) * XWS
                                          + (warpN + ti) * 58 + tj + g;
                    #pragma unroll
                    for (int nf = 0; nf < 7; ++nf) {
                        uint32_t b0 = bbase[nf * 8];
                        uint32_t b1 = bbase[4 * XWS + nf * 8];
                        #pragma unroll
                        for (int mf = 0; mf < 4; ++mf)
                            mma16(d[mf][nf], A[mf], b0, b1);
                    }
                }
            }
        }
    }

    // ---- epilogue ----
    #pragma unroll
    for (int mf = 0; mf < 4; ++mf) {
        int mrow = fh * 128 + (warpM * 4 + mf) * 16 + g;
        float* o0 = out + (size_t)(b * CH + mrow) * HW + (row0 + warpN) * 56;
        float* o8 = o0 + 8 * (size_t)HW;
        #pragma unroll
        for (int nf = 0; nf < 7; ++nf) {
            int pix = nf * 8 + 2 * t4;
            *(float2*)(o0 + pix) = make_float2(d[mf][nf][0], d[mf][nf][1]);
            *(float2*)(o8 + pix) = make_float2(d[mf][nf][2], d[mf][nf][3]);
        }
    }
}

// ============================================================================
// launch — inputs: x, w1, b1, w2, b2, w_att, b_att
// ============================================================================
extern "C" void kernel_launch(void* const* d_in, const int* in_sizes, int n_in,
                              void* d_out, int out_size)
{
    const float* x     = (const float*)d_in[0];
    const float* w1    = (const float*)d_in[1];
    const float* b1    = (const float*)d_in[2];
    const float* w2    = (const float*)d_in[3];
    const float* b2    = (const float*)d_in[4];
    const float* w_att = (const float*)d_in[5];
    const float* b_att = (const float*)d_in[6];
    float* out = (float*)d_out;

    cudaFuncSetAttribute(conv_mma, cudaFuncAttributeMaxDynamicSharedMemorySize,
                         CONV_SMEM);

    pool_kernel<<<BATCH * CH, 512>>>(x, w1, b1);
    dim3 ggrid(CH, BATCH);
    gen_kernel<<<ggrid, 256>>>(w2, b2, w_att, b_att);
    dim3 cgrid(14, 2, BATCH);
    conv_mma<<<cgrid, 256, CONV_SMEM>>>(x, out);
}

// round 15
// speedup vs baseline: 1.0177x; 1.0177x over previous
#include <cuda_runtime.h>
#include <cuda_fp16.h>
#include <cstdint>

#define BATCH 32
#define CH    256
#define HW    3136

// per-(b, f_half) stride in g_W: 144 k16_tiles * 2048 halves
#define WHALF 294912ull

// ---------------- scratch (device globals; no runtime allocation) ----------
__device__ float  g_maxi[BATCH * CH * 25];
__device__ float  g_wgt1[BATCH * CH * 9];
// fp16 weights in m16n8k16 fragment order:
// [b][f_half(2)][k16_tile(144)][f_tile(8)][lane(32)][reg(4)x half(2)]
__device__ __half g_W[(size_t)BATCH * CH * 9 * CH];

__constant__ int c_bin_start[5] = {0, 11, 22, 33, 44};

// ============================================================================
// Kernel 1: adaptive avg+max pool 56x56 -> 5x5, fused depthwise 3x3+relu.
// (proven 256-thread / 12-row-band version)
// ============================================================================
__global__ __launch_bounds__(256) void pool_kernel(
    const float* __restrict__ x, const float* __restrict__ w1,
    const float* __restrict__ b1)
{
    __shared__ float img[HW];
    __shared__ float rs[5][56], rm[5][56];
    __shared__ float avgb[25];
    int bc = blockIdx.x, c = bc & 255, t = threadIdx.x;

    const float4* src4 = (const float4*)(x + (size_t)bc * HW);
    float4* img4 = (float4*)img;
    for (int i = t; i < HW / 4; i += 256) img4[i] = src4[i];
    __syncthreads();

    for (int t2 = t; t2 < 280; t2 += 256) {
        int band = t2 / 56, col = t2 - band * 56;
        int r0 = c_bin_start[band];
        float s = 0.f, m = -3.402823466e38f;
        #pragma unroll
        for (int r = 0; r < 12; r++) {
            float v = img[(r0 + r) * 56 + col];
            s += v; m = fmaxf(m, v);
        }
        rs[band][col] = s; rm[band][col] = m;
    }
    __syncthreads();

    if (t < 25) {
        int bi = t / 5, bj = t % 5;
        int c0 = c_bin_start[bj];
        float s = 0.f, m = -3.402823466e38f;
        #pragma unroll
        for (int k = 0; k < 12; k++) {
            s += rs[bi][c0 + k];
            m = fmaxf(m, rm[bi][c0 + k]);
        }
        avgb[t] = s * (1.f / 144.f);
        g_maxi[bc * 25 + t] = m;
    }
    __syncthreads();

    if (t < 9) {
        int u = t / 3, v = t % 3;
        float acc = b1[c];
        #pragma unroll
        for (int i = 0; i < 3; i++)
            #pragma unroll
            for (int j = 0; j < 3; j++)
                acc += avgb[(u + i) * 5 + (v + j)] * w1[c * 9 + i * 3 + j];
        g_wgt1[bc * 9 + t] = fmaxf(acc, 0.f);
    }
}

// ============================================================================
// Kernel 2: weight generation, scatter-stored fp16 in m16n8k16 fragment order.
// ============================================================================
__global__ __launch_bounds__(256) void gen_kernel(
    const float* __restrict__ w2, const float* __restrict__ b2,
    const float* __restrict__ w_att, const float* __restrict__ b_att)
{
    int p = blockIdx.x, b = blockIdx.y, q = threadIdx.x;
    int bp = b * CH + p;

    __shared__ float maxi_s[25];
    __shared__ float wgt1_s[9];
    if (q < 25) maxi_s[q] = g_maxi[bp * 25 + q];
    if (q >= 32 && q < 41) wgt1_s[q - 32] = g_wgt1[bp * 9 + (q - 32)];
    __syncthreads();

    int cidx = p * CH + q;
    float wa[9];
    #pragma unroll
    for (int k = 0; k < 9; k++) wa[k] = w_att[cidx * 9 + k];
    float w2c = w2[cidx], b2c = b2[cidx], bac = b_att[cidx];

    int cg = q >> 5, ci = q & 31;
    int fh = p >> 7, fr = p & 127, ft = fr >> 4;
    int kk = ci & 15;
    int lane = ((fr & 7) << 2) | ((kk & 7) >> 1);
    int reg  = ((fr >> 3) & 1) | ((kk >> 3) << 1);
    int h    = kk & 1;
    __half* base = g_W + ((size_t)b * 2 + fh) * WHALF;
    size_t elem = ((size_t)ft * 32 + lane) * 8 + reg * 2 + h;

    #pragma unroll
    for (int u = 0; u < 3; u++)
        #pragma unroll
        for (int v = 0; v < 3; v++) {
            float s = bac;
            #pragma unroll
            for (int i = 0; i < 3; i++)
                #pragma unroll
                for (int j = 0; j < 3; j++)
                    s += maxi_s[(u + i) * 5 + (v + j)] * wa[i * 3 + j];
            float att = 1.f / (1.f + __expf(-s));
            float val = (wgt1_s[u * 3 + v] * w2c + b2c) * att;
            int tap = u * 3 + v;
            int kt = (cg * 9 + tap) * 2 + (ci >> 4);
            base[(size_t)kt * 2048 + elem] = __float2half_rn(val);
        }
}

// ============================================================================
// helpers
// ============================================================================
__device__ __forceinline__ uint32_t smem_u32(const void* p) {
    uint32_t a;
    asm("{ .reg .u64 t; cvta.to.shared.u64 t, %1; cvt.u32.u64 %0, t; }" : "=r"(a) : "l"(p));
    return a;
}
__device__ __forceinline__ uint32_t pkh2(float lo, float hi) {
    __half2 h = __floats2half2_rn(lo, hi);
    return *(uint32_t*)&h;
}
__device__ __forceinline__ void mma16(float* d, const uint4 a,
                                      uint32_t b0, uint32_t b1) {
    asm volatile(
        "mma.sync.aligned.m16n8k16.row.col.f32.f16.f16.f32 "
        "{%0,%1,%2,%3}, {%4,%5,%6,%7}, {%8,%9}, {%0,%1,%2,%3};"
        : "+f"(d[0]), "+f"(d[1]), "+f"(d[2]), "+f"(d[3])
        : "r"(a.x), "r"(a.y), "r"(a.z), "r"(a.w), "r"(b0), "r"(b1));
}
__device__ __forceinline__ void cpasync16(uint32_t dst, const void* src) {
    asm volatile("cp.async.cg.shared.global [%0], [%1], 16;" :: "r"(dst), "l"(src));
}
#define CP_COMMIT() asm volatile("cp.async.commit_group;" ::: "memory")
#define CP_WAIT0()  asm volatile("cp.async.wait_group 0;" ::: "memory")

// ============================================================================
// Kernel 3: fp16 m16n8k16 mma.sync implicit GEMM, occupancy 2.
// CTA = (b, f_quarter 64 filters, 4 rows x 56 px). Warps 2(M) x 4(N):
// warp tile = 32 filters x 56 px (2 m-frags x 7 n-frags, 56 accums).
// A stage = 3 taps x 64 filters = 12KB: per kt (6), quarter slice is
// 4 f_tiles * 256 halves = 128 x 16B chunks  ->  kt = idx>>7, rem = idx&127.
// grid 14 x 4 x 32 = 1792 CTAs, 2 per SM.
// ============================================================================
#define XWS     360                // uint32 stride per cpair
#define OFF_XR  23040              // xw32: 16*360*4 B
#define OFF_A   66048              // xraw: 32*84*16 = 43008 B
#define A_BUF   12288              // 6 kt * 1024 halves * 2 B
#define CONV_SMEM (OFF_A + 2 * A_BUF)   // 90624 B

__global__ void __launch_bounds__(256, 2)
conv_mma(const float* __restrict__ x, float* __restrict__ out)
{
    extern __shared__ char smem[];
    uint32_t* xw32 = (uint32_t*)smem;
    float* xraw = (float*)(smem + OFF_XR);
    const uint32_t sb = smem_u32(smem);
    const int tid = threadIdx.x, lid = tid & 31, wid = tid >> 5;
    const int g = lid >> 2, t4 = lid & 3;
    const int warpM = wid & 1, warpN = wid >> 1;    // 2 x 4
    const int b = blockIdx.z, fq = blockIdx.y, row0 = blockIdx.x * 4;

    const float* xb = x + (size_t)b * CH * HW;
    // quarter slice: f_half = fq>>1, f_tiles (fq&1)*4 .. +3
    const __half* wb = g_W + ((size_t)b * 2 + (fq >> 1)) * WHALF
                     + (size_t)(fq & 1) * 1024;

    float d[2][7][4];
    #pragma unroll
    for (int i = 0; i < 2; i++)
        #pragma unroll
        for (int j = 0; j < 7; j++)
            #pragma unroll
            for (int k = 0; k < 4; k++) d[i][j][k] = 0.f;

    // ---- A stage: 12KB copy; 6 kt x 128 chunks of 16B per kt ----
    auto stageA = [&](int stageIdx, int buf) {
        const __half* src = wb + (size_t)stageIdx * 12288;   // 6 kt * 2048
        uint32_t dbase = sb + OFF_A + (uint32_t)buf * A_BUF;
        #pragma unroll
        for (int i = 0; i < 3; ++i) {
            int idx = i * 256 + tid;            // 0..767
            int kt = idx >> 7, rem = idx & 127; // 128 chunks per kt slice
            cpasync16(dbase + (uint32_t)idx * 16, src + kt * 2048 + rem * 8);
        }
        CP_COMMIT();
    };
    // ---- X prefetch: raw 32-ch fp32 window -> xraw ----
    auto stageX = [&](int cg) {
        for (int i = tid; i < 32 * 84; i += 256) {
            int c2 = i / 84, rem = i - c2 * 84;
            int rw = rem / 14, gq = rem - rw * 14;
            int grow = row0 - 1 + rw;
            if ((unsigned)grow < 56u)
                cpasync16(sb + OFF_XR + (uint32_t)i * 16,
                          xb + (size_t)(cg * 32 + c2) * HW + grow * 56 + 4 * gq);
        }
        CP_COMMIT();
    };

    // zero packed window once (halo stays zero)
    for (int i = tid; i < (16 * XWS) / 4; i += 256)
        ((uint4*)xw32)[i] = make_uint4(0, 0, 0, 0);
    stageX(0);
    stageA(0, 0);

    int stage = 0;
    for (int cg = 0; cg < 8; ++cg) {
        CP_WAIT0();
        __syncthreads();
        // ---- pack raw fp32 -> fp16x2 channel pairs ----
        for (int i = tid; i < 16 * 84; i += 256) {
            int cp = i / 84, rem = i - cp * 84;
            int rw = rem / 14, gq = rem - rw * 14;
            int grow = row0 - 1 + rw;
            if ((unsigned)grow < 56u) {
                float4 va = ((const float4*)xraw)[(2 * cp) * 84 + rem];
                float4 vb = ((const float4*)xraw)[(2 * cp + 1) * 84 + rem];
                uint32_t* dst = xw32 + cp * XWS + rw * 58 + 4 * gq + 1;
                dst[0] = pkh2(va.x, vb.x);
                dst[1] = pkh2(va.y, vb.y);
                dst[2] = pkh2(va.z, vb.z);
                dst[3] = pkh2(va.w, vb.w);
            }
        }
        __syncthreads();

        for (int s = 0; s < 3; ++s, ++stage) {
            const int buf = stage & 1;
            if (s > 0) {
                CP_WAIT0();
                __syncthreads();
            }
            if (s < 2) {
                stageA(stage + 1, buf ^ 1);
            } else {
                if (cg < 7) stageX(cg + 1);
                if (stage + 1 < 24) stageA(stage + 1, buf ^ 1);
            }

            const uint32_t* as = (const uint32_t*)(smem + OFF_A + buf * A_BUF);
            #pragma unroll
            for (int tapo = 0; tapo < 3; ++tapo) {
                const int tap = s * 3 + tapo;
                const int ti = tap / 3, tj = tap - ti * 3;
                #pragma unroll
                for (int ksh = 0; ksh < 2; ++ksh) {
                    uint4 A[2];
                    const uint32_t* abase = as
                        + ((tapo * 2 + ksh) * 4 + warpM * 2) * 128 + lid * 4;
                    A[0] = *(const uint4*)(abase);
                    A[1] = *(const uint4*)(abase + 128);
                    const uint32_t* bbase = xw32 + (ksh * 8 + t4) * XWS
                                          + (warpN + ti) * 58 + tj + g;
                    #pragma unroll
                    for (int nf = 0; nf < 7; ++nf) {
                        uint32_t b0 = bbase[nf * 8];
                        uint32_t b1 = bbase[4 * XWS + nf * 8];
                        mma16(d[0][nf], A[0], b0, b1);
                        mma16(d[1][nf], A[1], b0, b1);
                    }
                }
            }
        }
    }

    // ---- epilogue ----
    #pragma unroll
    for (int mf = 0; mf < 2; ++mf) {
        int mrow = fq * 64 + (warpM * 2 + mf) * 16 + g;
        float* o0 = out + (size_t)(b * CH + mrow) * HW + (row0 + warpN) * 56;
        float* o8 = o0 + 8 * (size_t)HW;
        #pragma unroll
        for (int nf = 0; nf < 7; ++nf) {
            int pix = nf * 8 + 2 * t4;
            *(float2*)(o0 + pix) = make_float2(d[mf][nf][0], d[mf][nf][1]);
            *(float2*)(o8 + pix) = make_float2(d[mf][nf][2], d[mf][nf][3]);
        }
    }
}

// ============================================================================
// launch — inputs: x, w1, b1, w2, b2, w_att, b_att
// ============================================================================
extern "C" void kernel_launch(void* const* d_in, const int* in_sizes, int n_in,
                              void* d_out, int out_size)
{
    const float* x     = (const float*)d_in[0];
    const float* w1    = (const float*)d_in[1];
    const float* b1    = (const float*)d_in[2];
    const float* w2    = (const float*)d_in[3];
    const float* b2    = (const float*)d_in[4];
    const float* w_att = (const float*)d_in[5];
    const float* b_att = (const float*)d_in[6];
    float* out = (float*)d_out;

    cudaFuncSetAttribute(conv_mma, cudaFuncAttributeMaxDynamicSharedMemorySize,
                         CONV_SMEM);

    pool_kernel<<<BATCH * CH, 256>>>(x, w1, b1);
    dim3 ggrid(CH, BATCH);
    gen_kernel<<<ggrid, 256>>>(w2, b2, w_att, b_att);
    dim3 cgrid(14, 4, BATCH);
    conv_mma<<<cgrid, 256, CONV_SMEM>>>(x, out);
}

// round 17
// speedup vs baseline: 1.1069x; 1.0877x over previous
#include <cuda_runtime.h>
#include <cuda_fp16.h>
#include <cstdint>

#define BATCH 32
#define CH    256
#define HW    3136

// per-(b, f_half) stride in g_W: 144 k16_tiles * 2048 halves
#define WHALF 294912ull

// ---------------- scratch (device globals; no runtime allocation) ----------
__device__ float  g_maxi[BATCH * CH * 25];
__device__ float  g_wgt1[BATCH * CH * 9];
// fp16 weights in m16n8k16 fragment order:
// [b][f_half(2)][k16_tile(144)][f_tile(8)][lane(32)][reg(4)x half(2)]
__device__ __align__(16) __half g_W[(size_t)BATCH * CH * 9 * CH];
// channel-pair-packed fp16 x: g_xp[b][cpair(128)][row(56)][col(56)] as u32
__device__ __align__(16) uint32_t g_xp[(size_t)BATCH * 128 * HW];

__constant__ int c_bin_start[5] = {0, 11, 22, 33, 44};

__device__ __forceinline__ uint32_t pkh2(float lo, float hi) {
    __half2 h = __floats2half2_rn(lo, hi);
    return *(uint32_t*)&h;
}

// ============================================================================
// Kernel 1: per-(b, channel-pair): adaptive avg+max pool + depthwise 3x3+relu
// for BOTH channels, AND emit the fp16x2-packed x image (g_xp).
// grid = 4096 (b*128+cp), 256 threads.
// ============================================================================
__global__ __launch_bounds__(256) void pool_kernel(
    const float* __restrict__ x, const float* __restrict__ w1,
    const float* __restrict__ b1)
{
    __shared__ float img[2][HW];
    __shared__ float rs[2][5][56], rm[2][5][56];
    __shared__ float avgb[2][25];
    int bc2 = blockIdx.x, cp = bc2 & 127, b = bc2 >> 7, t = threadIdx.x;
    int c0 = 2 * cp;

    const float4* src0 = (const float4*)(x + ((size_t)b * CH + c0) * HW);
    const float4* src1 = (const float4*)(x + ((size_t)b * CH + c0 + 1) * HW);
    float4* i40 = (float4*)img[0];
    float4* i41 = (float4*)img[1];
    for (int i = t; i < HW / 4; i += 256) { i40[i] = src0[i]; i41[i] = src1[i]; }
    __syncthreads();

    // packed fp16x2 x image out (both channels interleaved per element)
    {
        uint4* dst = (uint4*)(g_xp + ((size_t)b * 128 + cp) * HW);
        for (int i = t; i < HW / 4; i += 256) {
            float4 va = i40[i], vb = i41[i];
            dst[i] = make_uint4(pkh2(va.x, vb.x), pkh2(va.y, vb.y),
                                pkh2(va.z, vb.z), pkh2(va.w, vb.w));
        }
    }

    // band reduction: 2 channels x 5 bands x 56 cols
    for (int t2 = t; t2 < 560; t2 += 256) {
        int ch = t2 >= 280, r2 = t2 - ch * 280;
        int band = r2 / 56, col = r2 - band * 56;
        int r0 = c_bin_start[band];
        float s = 0.f, m = -3.402823466e38f;
        #pragma unroll
        for (int r = 0; r < 12; r++) {
            float v = img[ch][(r0 + r) * 56 + col];
            s += v; m = fmaxf(m, v);
        }
        rs[ch][band][col] = s; rm[ch][band][col] = m;
    }
    __syncthreads();

    if (t < 50) {
        int ch = t >= 25, bin = t - ch * 25;
        int bi = bin / 5, bj = bin % 5;
        int cc0 = c_bin_start[bj];
        float s = 0.f, m = -3.402823466e38f;
        #pragma unroll
        for (int k = 0; k < 12; k++) {
            s += rs[ch][bi][cc0 + k];
            m = fmaxf(m, rm[ch][bi][cc0 + k]);
        }
        avgb[ch][bin] = s * (1.f / 144.f);
        g_maxi[((size_t)b * CH + c0 + ch) * 25 + bin] = m;
    }
    __syncthreads();

    if (t < 18) {
        int ch = t >= 9, tp = t - ch * 9;
        int u = tp / 3, v = tp % 3;
        int c = c0 + ch;
        float acc = b1[c];
        #pragma unroll
        for (int i = 0; i < 3; i++)
            #pragma unroll
            for (int j = 0; j < 3; j++)
                acc += avgb[ch][(u + i) * 5 + (v + j)] * w1[c * 9 + i * 3 + j];
        g_wgt1[((size_t)b * CH + c) * 9 + tp] = fmaxf(acc, 0.f);
    }
}

// ============================================================================
// Kernel 2: weight generation, scatter-stored fp16 in m16n8k16 fragment order.
// ============================================================================
__global__ __launch_bounds__(256) void gen_kernel(
    const float* __restrict__ w2, const float* __restrict__ b2,
    const float* __restrict__ w_att, const float* __restrict__ b_att)
{
    int p = blockIdx.x, b = blockIdx.y, q = threadIdx.x;
    int bp = b * CH + p;

    __shared__ float maxi_s[25];
    __shared__ float wgt1_s[9];
    if (q < 25) maxi_s[q] = g_maxi[bp * 25 + q];
    if (q >= 32 && q < 41) wgt1_s[q - 32] = g_wgt1[bp * 9 + (q - 32)];
    __syncthreads();

    int cidx = p * CH + q;
    float wa[9];
    #pragma unroll
    for (int k = 0; k < 9; k++) wa[k] = w_att[cidx * 9 + k];
    float w2c = w2[cidx], b2c = b2[cidx], bac = b_att[cidx];

    int cg = q >> 5, ci = q & 31;
    int fh = p >> 7, fr = p & 127, ft = fr >> 4;
    int kk = ci & 15;
    int lane = ((fr & 7) << 2) | ((kk & 7) >> 1);
    int reg  = ((fr >> 3) & 1) | ((kk >> 3) << 1);
    int h    = kk & 1;
    __half* base = g_W + ((size_t)b * 2 + fh) * WHALF;
    size_t elem = ((size_t)ft * 32 + lane) * 8 + reg * 2 + h;

    #pragma unroll
    for (int u = 0; u < 3; u++)
        #pragma unroll
        for (int v = 0; v < 3; v++) {
            float s = bac;
            #pragma unroll
            for (int i = 0; i < 3; i++)
                #pragma unroll
                for (int j = 0; j < 3; j++)
                    s += maxi_s[(u + i) * 5 + (v + j)] * wa[i * 3 + j];
            float att = 1.f / (1.f + __expf(-s));
            float val = (wgt1_s[u * 3 + v] * w2c + b2c) * att;
            int tap = u * 3 + v;
            int kt = (cg * 9 + tap) * 2 + (ci >> 4);
            base[(size_t)kt * 2048 + elem] = __float2half_rn(val);
        }
}

// ============================================================================
// helpers
// ============================================================================
__device__ __forceinline__ uint32_t smem_u32(const void* p) {
    uint32_t a;
    asm("{ .reg .u64 t; cvta.to.shared.u64 t, %1; cvt.u32.u64 %0, t; }" : "=r"(a) : "l"(p));
    return a;
}
__device__ __forceinline__ void mma16(float* d, const uint4 a,
                                      uint32_t b0, uint32_t b1) {
    asm volatile(
        "mma.sync.aligned.m16n8k16.row.col.f32.f16.f16.f32 "
        "{%0,%1,%2,%3}, {%4,%5,%6,%7}, {%8,%9}, {%0,%1,%2,%3};"
        : "+f"(d[0]), "+f"(d[1]), "+f"(d[2]), "+f"(d[3])
        : "r"(a.x), "r"(a.y), "r"(a.z), "r"(a.w), "r"(b0), "r"(b1));
}
__device__ __forceinline__ void cpasync16(uint32_t dst, const void* src) {
    asm volatile("cp.async.cg.shared.global [%0], [%1], 16;" :: "r"(dst), "l"(src));
}
#define CP_COMMIT() asm volatile("cp.async.commit_group;" ::: "memory")
#define CP_WAIT0()  asm volatile("cp.async.wait_group 0;" ::: "memory")

// ============================================================================
// Kernel 3: fp16 m16n8k16 mma.sync implicit GEMM.
// CTA = (b, f_half 128 filters, 4 rows x 56 px). Warps 2(M) x 4(N).
// x windows cp.async'd DIRECTLY from pre-packed g_xp into double-buffered
// padded windows (no per-cg pack phase). Window: [cpair(16)][row(6)][64 u32],
// data at cols 4..59, halo zeros at 3 & 60; cpair stride 392 (%32==8).
// A stage = 3 taps = 24KB linear, double-buffered (proven R10 discipline).
// ============================================================================
#define XWS     392                // u32 stride per cpair
#define XW_BUF  25088              // 16*392*4 B per window buffer
#define OFF_A   50176              // after 2 window buffers
#define A_BUF   24576              // 6 kt * 2048 halves * 2 B
#define CONV_SMEM (OFF_A + 2 * A_BUF)   // 99328 B

__global__ void __launch_bounds__(256, 1)
conv_mma(float* __restrict__ out)
{
    extern __shared__ char smem[];
    const uint32_t sb = smem_u32(smem);
    const int tid = threadIdx.x, lid = tid & 31, wid = tid >> 5;
    const int g = lid >> 2, t4 = lid & 3;
    const int warpM = wid & 1, warpN = wid >> 1;    // 2 x 4
    const int b = blockIdx.z, fh = blockIdx.y, row0 = blockIdx.x * 4;

    const __half* wb = g_W + ((size_t)b * 2 + fh) * WHALF;
    const uint32_t* xpb = g_xp + (size_t)b * 128 * HW;

    float d[4][7][4];
    #pragma unroll
    for (int i = 0; i < 4; i++)
        #pragma unroll
        for (int j = 0; j < 7; j++)
            #pragma unroll
            for (int k = 0; k < 4; k++) d[i][j][k] = 0.f;

    // ---- A stage: 24KB linear copy (stage = 3 taps = 6 k16-tiles) ----
    auto stageA = [&](int stageIdx, int buf) {
        const __half* src = wb + (size_t)stageIdx * 12288;
        uint32_t dbase = sb + OFF_A + (uint32_t)buf * A_BUF;
        #pragma unroll
        for (int i = 0; i < 6; ++i) {
            int idx = i * 256 + tid;
            cpasync16(dbase + (uint32_t)idx * 16, src + idx * 8);
        }
        CP_COMMIT();
    };
    // ---- X stage: packed window for cg -> window buffer xbuf ----
    auto stageX = [&](int cg, int xbuf) {
        for (int i = tid; i < 16 * 84; i += 256) {
            int cp = i / 84, rem = i - cp * 84;
            int rw = rem / 14, k = rem - rw * 14;
            int grow = row0 - 1 + rw;
            if ((unsigned)grow < 56u)
                cpasync16(sb + (uint32_t)xbuf * XW_BUF
                             + (uint32_t)(cp * XWS + rw * 64 + 4 + 4 * k) * 4,
                          xpb + (size_t)(cg * 16 + cp) * HW + grow * 56 + 4 * k);
        }
        CP_COMMIT();
    };

    // zero both window buffers once (halos + invalid rows stay zero)
    for (int i = tid; i < (2 * XW_BUF) / 16; i += 256)
        ((uint4*)smem)[i] = make_uint4(0, 0, 0, 0);
    __syncthreads();
    stageX(0, 0);
    stageA(0, 0);

    int stage = 0;
    for (int cg = 0; cg < 8; ++cg) {
        const int wbuf = cg & 1;
        CP_WAIT0();                 // X(cg) + A(3cg) resident
        __syncthreads();
        const uint32_t* xwb = (const uint32_t*)(smem + wbuf * XW_BUF);

        for (int s = 0; s < 3; ++s, ++stage) {
            const int buf = stage & 1;
            if (s > 0) {
                CP_WAIT0();
                __syncthreads();
            }
            if (s < 2) {
                stageA(stage + 1, buf ^ 1);
            } else {
                if (cg < 7) stageX(cg + 1, wbuf ^ 1);
                if (stage + 1 < 24) stageA(stage + 1, buf ^ 1);
            }

            const uint32_t* as = (const uint32_t*)(smem + OFF_A + buf * A_BUF);
            #pragma unroll
            for (int tapo = 0; tapo < 3; ++tapo) {
                const int tap = s * 3 + tapo;
                const int ti = tap / 3, tj = tap - ti * 3;
                #pragma unroll
                for (int ksh = 0; ksh < 2; ++ksh) {
                    uint4 A[4];
                    const uint32_t* abase = as
                        + ((tapo * 2 + ksh) * 8 + warpM * 4) * 128 + lid * 4;
                    #pragma unroll
                    for (int mf = 0; mf < 4; ++mf)
                        A[mf] = *(const uint4*)(abase + mf * 128);
                    const uint32_t* bbase = xwb + (ksh * 8 + t4) * XWS
                                          + (warpN + ti) * 64 + 3 + tj + g;
                    #pragma unroll
                    for (int nf = 0; nf < 7; ++nf) {
                        uint32_t b0 = bbase[nf * 8];
                        uint32_t b1 = bbase[4 * XWS + nf * 8];
                        #pragma unroll
                        for (int mf = 0; mf < 4; ++mf)
                            mma16(d[mf][nf], A[mf], b0, b1);
                    }
                }
            }
        }
    }

    // ---- epilogue ----
    #pragma unroll
    for (int mf = 0; mf < 4; ++mf) {
        int mrow = fh * 128 + (warpM * 4 + mf) * 16 + g;
        float* o0 = out + (size_t)(b * CH + mrow) * HW + (row0 + warpN) * 56;
        float* o8 = o0 + 8 * (size_t)HW;
        #pragma unroll
        for (int nf = 0; nf < 7; ++nf) {
            int pix = nf * 8 + 2 * t4;
            *(float2*)(o0 + pix) = make_float2(d[mf][nf][0], d[mf][nf][1]);
            *(float2*)(o8 + pix) = make_float2(d[mf][nf][2], d[mf][nf][3]);
        }
    }
}

// ============================================================================
// launch — inputs: x, w1, b1, w2, b2, w_att, b_att
// ============================================================================
extern "C" void kernel_launch(void* const* d_in, const int* in_sizes, int n_in,
                              void* d_out, int out_size)
{
    const float* x     = (const float*)d_in[0];
    const float* w1    = (const float*)d_in[1];
    const float* b1    = (const float*)d_in[2];
    const float* w2    = (const float*)d_in[3];
    const float* b2    = (const float*)d_in[4];
    const float* w_att = (const float*)d_in[5];
    const float* b_att = (const float*)d_in[6];
    float* out = (float*)d_out;

    cudaFuncSetAttribute(conv_mma, cudaFuncAttributeMaxDynamicSharedMemorySize,
                         CONV_SMEM);

    pool_kernel<<<BATCH * 128, 256>>>(x, w1, b1);
    dim3 ggrid(CH, BATCH);
    gen_kernel<<<ggrid, 256>>>(w2, b2, w_att, b_att);
    dim3 cgrid(14, 2, BATCH);
    conv_mma<<<cgrid, 256, CONV_SMEM>>>(out);
}